// round 14
// baseline (speedup 1.0000x reference)
#include <cuda_runtime.h>

// ---------------------------------------------------------------------------
// ChebConv x4 GNN on GB300.  N=100000 nodes, E=1600000 directed edges
// (symmetrized), HID=128, K=4 Chebyshev order.
//
// R8:  serial scan -> warp-aggregated atomic slice allocation.
// R9:  2-stage double-buffered GEMM mainloop.
// R10: stride detect folded into k_init.                    (2052 us)
// R11: k_apply eliminated — BN fused into SpMM#1 gather, SpMM#2 prev term,
//      and the GEMM A-load (T0 never materialized; g_A rows 512 -> 384).
//      (resubmitted unchanged; broker timeouts R11/R12/R13)
// ---------------------------------------------------------------------------

#define NNODES 100000
#define NEDGES 1600000
#define HIDDEN 128
#define NEG_SLOPE 0.01f
#define ASTRIDE 384     // g_A row: [T1|T2|T3]

// ------------------------------- scratch -----------------------------------
__device__ float g_A[(size_t)NNODES * ASTRIDE];
__device__ float g_Y[(size_t)NNODES * HIDDEN];   // pre-BN activations
__device__ float g_A1[(size_t)NNODES * 12];      // layer-1 [T0|T1|T2|T3] x 3
__device__ int   g_deg[NNODES];
__device__ int   g_cur[NNODES];
__device__ int   g_rowstart[NNODES];
__device__ int2  g_edge[NEDGES];                 // (col, enorm-bits)
__device__ float g_dinv[NNODES];
__device__ float g_colsum[3][HIDDEN];            // per-BN-layer stats
__device__ float g_colsumsq[3][HIDDEN];
__device__ int   g_estride;                      // 1 = int32, 2 = int64
__device__ int   g_total;                        // slice allocation counter

// ------------------------------ helpers ------------------------------------
__device__ __forceinline__ void ffma2(float2& d, const float2 a, const float2 b) {
    asm volatile("fma.rn.f32x2 %0, %1, %2, %0;"
                 : "+l"(reinterpret_cast<unsigned long long&>(d))
                 : "l"(reinterpret_cast<const unsigned long long&>(a)),
                   "l"(reinterpret_cast<const unsigned long long&>(b)));
}

__device__ __forceinline__ void bn_params(const float* gamma, const float* beta,
                                          int layer, int c, float& sc, float& sh) {
    const float inv_n = 1.0f / (float)NNODES;
    float mu = g_colsum[layer][c] * inv_n;
    float var = fmaxf(g_colsumsq[layer][c] * inv_n - mu * mu, 0.f);
    float s = gamma[c] * rsqrtf(var + 1e-5f);
    sc = s;
    sh = beta[c] - mu * s;
}

// ------------------------------ CSR build ----------------------------------
__global__ void k_init(const float* __restrict__ x, const int* __restrict__ ed) {
    int i = blockIdx.x * blockDim.x + threadIdx.x;
    int gs = gridDim.x * blockDim.x;
    for (int j = i; j < NNODES; j += gs) {
        g_deg[j] = 0;
        g_cur[j] = 0;
        g_A1[j * 12 + 0] = x[j * 3 + 0];
        g_A1[j * 12 + 1] = x[j * 3 + 1];
        g_A1[j * 12 + 2] = x[j * 3 + 2];
    }
    if (blockIdx.x == 0) {
        if (threadIdx.x == 0) g_total = 0;
        if (threadIdx.x < HIDDEN) {
            for (int l = 0; l < 3; l++) {
                g_colsum[l][threadIdx.x] = 0.f;
                g_colsumsq[l][threadIdx.x] = 0.f;
            }
        }
        if (threadIdx.x < 32) {
            int lane = threadIdx.x;
            bool any = false;
            for (int k2 = 1 + 2 * lane; k2 < 4096; k2 += 64) any |= (ed[k2] != 0);
            any = __any_sync(0xffffffffu, any);
            if (lane == 0) g_estride = any ? 1 : 2;
        }
    }
}

__global__ void k_count(const int* __restrict__ ed) {
    int st = g_estride;
    int i = blockIdx.x * blockDim.x + threadIdx.x;
    int gs = gridDim.x * blockDim.x;
    if (st == 1) {
        const int* dstp = ed + NEDGES;
        for (int e = i; e < NEDGES; e += gs)
            atomicAdd(&g_deg[dstp[e]], 1);
    } else {
        const long long* dstp = (const long long*)ed + NEDGES;
        for (int e = i; e < NEDGES; e += gs)
            atomicAdd(&g_deg[(int)dstp[e]], 1);
    }
}

__global__ void k_alloc() {
    const int NPAD = (NNODES + 31) & ~31;
    int i = blockIdx.x * blockDim.x + threadIdx.x;
    int gs = gridDim.x * blockDim.x;
    int lane = threadIdx.x & 31;
    for (int j = i; j < NPAD; j += gs) {
        int d = (j < NNODES) ? g_deg[j] : 0;
        int pre = d;
#pragma unroll
        for (int o = 1; o < 32; o <<= 1) {
            int v = __shfl_up_sync(0xffffffffu, pre, o);
            if (lane >= o) pre += v;
        }
        int wtot = __shfl_sync(0xffffffffu, pre, 31);
        int base = 0;
        if (lane == 31) base = atomicAdd(&g_total, wtot);
        base = __shfl_sync(0xffffffffu, base, 31);
        if (j < NNODES) {
            g_rowstart[j] = base + pre - d;
            g_dinv[j] = (d > 0) ? rsqrtf((float)d) : 0.f;
        }
    }
}

__global__ void k_fill(const int* __restrict__ ed) {
    int st = g_estride;
    int i = blockIdx.x * blockDim.x + threadIdx.x;
    int gs = gridDim.x * blockDim.x;
    if (st == 1) {
        const int* srcp = ed;
        const int* dstp = ed + NEDGES;
        for (int e = i; e < NEDGES; e += gs) {
            int s = srcp[e], d = dstp[e];
            int pos = g_rowstart[d] + atomicAdd(&g_cur[d], 1);
            float w = -g_dinv[s] * g_dinv[d];
            g_edge[pos] = make_int2(s, __float_as_int(w));
        }
    } else {
        const long long* srcp = (const long long*)ed;
        const long long* dstp = (const long long*)ed + NEDGES;
        for (int e = i; e < NEDGES; e += gs) {
            int s = (int)srcp[e], d = (int)dstp[e];
            int pos = g_rowstart[d] + atomicAdd(&g_cur[d], 1);
            float w = -g_dinv[s] * g_dinv[d];
            g_edge[pos] = make_int2(s, __float_as_int(w));
        }
    }
}

// --------------------------- layer 1 (3-wide) ------------------------------
__global__ void k_spmm3(int in_off, int out_off, int prev_off, int mode) {
    int i = blockIdx.x * blockDim.x + threadIdx.x;
    int gs = gridDim.x * blockDim.x;
    for (int r = i; r < NNODES; r += gs) {
        int b = g_rowstart[r], e2 = b + g_deg[r];
        float a0 = 0.f, a1 = 0.f, a2 = 0.f;
        for (int e = b; e < e2; e++) {
            int2 ew = g_edge[e];
            float w = __int_as_float(ew.y);
            const float* p = &g_A1[(size_t)ew.x * 12 + in_off];
            a0 += w * p[0]; a1 += w * p[1]; a2 += w * p[2];
        }
        if (mode) {
            const float* pr = &g_A1[(size_t)r * 12 + prev_off];
            a0 = 2.f * a0 - pr[0]; a1 = 2.f * a1 - pr[1]; a2 = 2.f * a2 - pr[2];
        }
        float* q = &g_A1[(size_t)r * 12 + out_off];
        q[0] = a0; q[1] = a1; q[2] = a2;
    }
}

// K=12 GEMM + leaky + fused BN-stats accumulation (layer-0 stats).
__global__ void k_gemm12(const float* __restrict__ W, const float* __restrict__ bias) {
    __shared__ float Ws[12 * 128];
    int c = threadIdx.x;
    for (int j = 0; j < 12; j++) Ws[j * 128 + c] = W[j * 128 + c];
    __syncthreads();
    float b = bias[c];
    float s = 0.f, s2 = 0.f;
    for (int i = blockIdx.x; i < NNODES; i += gridDim.x) {
        const float* ar = &g_A1[(size_t)i * 12];
        float acc = b;
#pragma unroll
        for (int j = 0; j < 12; j++) acc += ar[j] * Ws[j * 128 + c];
        acc = (acc >= 0.f) ? acc : NEG_SLOPE * acc;   // leaky
        g_Y[(size_t)i * 128 + c] = acc;
        s += acc; s2 += acc * acc;
    }
    atomicAdd(&g_colsum[0][c], s);
    atomicAdd(&g_colsumsq[0][c], s2);
}

// --------------------------- 128-wide SpMM ---------------------------------
// Warp per row; lane owns 4 columns (float4).  bn_mode:
//   1: T1 = L bn(Y)         (gather from g_Y, per-column affine on the fly)
//   2: T2 = 2 L T1 - bn(Y)  (gather from g_A[in_off], prev = bn(Y[r]))
//   0: T3 = 2 L T2 - T1     (plain, all from g_A)
__global__ void __launch_bounds__(256) k_spmm128(int in_off, int out_off,
                                                 int prev_off, int bn_mode,
                                                 const float* __restrict__ gamma,
                                                 const float* __restrict__ beta,
                                                 int layer) {
    int warp = blockIdx.x * 8 + (threadIdx.x >> 5);
    int lane = threadIdx.x & 31;
    if (warp >= NNODES) return;
    int r = warp;
    int b = g_rowstart[r], e2 = b + g_deg[r];
    int c4 = lane * 4;

    float4 sc = make_float4(0.f, 0.f, 0.f, 0.f);
    float4 sh = make_float4(0.f, 0.f, 0.f, 0.f);
    if (bn_mode) {
        bn_params(gamma, beta, layer, c4 + 0, sc.x, sh.x);
        bn_params(gamma, beta, layer, c4 + 1, sc.y, sh.y);
        bn_params(gamma, beta, layer, c4 + 2, sc.z, sh.z);
        bn_params(gamma, beta, layer, c4 + 3, sc.w, sh.w);
    }

    float4 acc0 = make_float4(0.f, 0.f, 0.f, 0.f);
    float4 acc1 = make_float4(0.f, 0.f, 0.f, 0.f);
    float4 acc2 = make_float4(0.f, 0.f, 0.f, 0.f);
    float4 acc3 = make_float4(0.f, 0.f, 0.f, 0.f);

    int e = b;
    if (bn_mode == 1) {
        // gather from g_Y (128-stride), affine-transform each gathered value
        for (; e + 4 <= e2; e += 4) {
            int2 h0 = g_edge[e];
            int2 h1 = g_edge[e + 1];
            int2 h2 = g_edge[e + 2];
            int2 h3 = g_edge[e + 3];
            float4 v0 = *(const float4*)&g_Y[(size_t)h0.x * 128 + c4];
            float4 v1 = *(const float4*)&g_Y[(size_t)h1.x * 128 + c4];
            float4 v2 = *(const float4*)&g_Y[(size_t)h2.x * 128 + c4];
            float4 v3 = *(const float4*)&g_Y[(size_t)h3.x * 128 + c4];
            float w0 = __int_as_float(h0.y), w1 = __int_as_float(h1.y);
            float w2 = __int_as_float(h2.y), w3 = __int_as_float(h3.y);
            acc0.x += w0 * (v0.x * sc.x + sh.x); acc0.y += w0 * (v0.y * sc.y + sh.y);
            acc0.z += w0 * (v0.z * sc.z + sh.z); acc0.w += w0 * (v0.w * sc.w + sh.w);
            acc1.x += w1 * (v1.x * sc.x + sh.x); acc1.y += w1 * (v1.y * sc.y + sh.y);
            acc1.z += w1 * (v1.z * sc.z + sh.z); acc1.w += w1 * (v1.w * sc.w + sh.w);
            acc2.x += w2 * (v2.x * sc.x + sh.x); acc2.y += w2 * (v2.y * sc.y + sh.y);
            acc2.z += w2 * (v2.z * sc.z + sh.z); acc2.w += w2 * (v2.w * sc.w + sh.w);
            acc3.x += w3 * (v3.x * sc.x + sh.x); acc3.y += w3 * (v3.y * sc.y + sh.y);
            acc3.z += w3 * (v3.z * sc.z + sh.z); acc3.w += w3 * (v3.w * sc.w + sh.w);
        }
        for (; e < e2; e++) {
            int2 h = g_edge[e];
            float w = __int_as_float(h.y);
            float4 v = *(const float4*)&g_Y[(size_t)h.x * 128 + c4];
            acc0.x += w * (v.x * sc.x + sh.x); acc0.y += w * (v.y * sc.y + sh.y);
            acc0.z += w * (v.z * sc.z + sh.z); acc0.w += w * (v.w * sc.w + sh.w);
        }
    } else {
        int c = in_off + c4;
        for (; e + 4 <= e2; e += 4) {
            int2 h0 = g_edge[e];
            int2 h1 = g_edge[e + 1];
            int2 h2 = g_edge[e + 2];
            int2 h3 = g_edge[e + 3];
            float4 v0 = *(const float4*)&g_A[(size_t)h0.x * ASTRIDE + c];
            float4 v1 = *(const float4*)&g_A[(size_t)h1.x * ASTRIDE + c];
            float4 v2 = *(const float4*)&g_A[(size_t)h2.x * ASTRIDE + c];
            float4 v3 = *(const float4*)&g_A[(size_t)h3.x * ASTRIDE + c];
            float w0 = __int_as_float(h0.y), w1 = __int_as_float(h1.y);
            float w2 = __int_as_float(h2.y), w3 = __int_as_float(h3.y);
            acc0.x += w0 * v0.x; acc0.y += w0 * v0.y;
            acc0.z += w0 * v0.z; acc0.w += w0 * v0.w;
            acc1.x += w1 * v1.x; acc1.y += w1 * v1.y;
            acc1.z += w1 * v1.z; acc1.w += w1 * v1.w;
            acc2.x += w2 * v2.x; acc2.y += w2 * v2.y;
            acc2.z += w2 * v2.z; acc2.w += w2 * v2.w;
            acc3.x += w3 * v3.x; acc3.y += w3 * v3.y;
            acc3.z += w3 * v3.z; acc3.w += w3 * v3.w;
        }
        for (; e < e2; e++) {
            int2 h = g_edge[e];
            float w = __int_as_float(h.y);
            float4 v = *(const float4*)&g_A[(size_t)h.x * ASTRIDE + c];
            acc0.x += w * v.x; acc0.y += w * v.y;
            acc0.z += w * v.z; acc0.w += w * v.w;
        }
    }

    float4 acc = make_float4((acc0.x + acc1.x) + (acc2.x + acc3.x),
                             (acc0.y + acc1.y) + (acc2.y + acc3.y),
                             (acc0.z + acc1.z) + (acc2.z + acc3.z),
                             (acc0.w + acc1.w) + (acc2.w + acc3.w));
    if (bn_mode == 2) {
        float4 y = *(const float4*)&g_Y[(size_t)r * 128 + c4];
        acc.x = 2.f * acc.x - (y.x * sc.x + sh.x);
        acc.y = 2.f * acc.y - (y.y * sc.y + sh.y);
        acc.z = 2.f * acc.z - (y.z * sc.z + sh.z);
        acc.w = 2.f * acc.w - (y.w * sc.w + sh.w);
    } else if (bn_mode == 0) {
        float4 pr = *(const float4*)&g_A[(size_t)r * ASTRIDE + prev_off + c4];
        acc.x = 2.f * acc.x - pr.x;
        acc.y = 2.f * acc.y - pr.y;
        acc.z = 2.f * acc.z - pr.z;
        acc.w = 2.f * acc.w - pr.w;
    }
    *(float4*)&g_A[(size_t)r * ASTRIDE + out_off + c4] = acc;
}

// ------------------------- K=512 fp32 GEMM (f32x2) -------------------------
// A row m = [bn(Y[m]) | T1 | T2 | T3]; first 128 K-cols read g_Y with
// smem-staged scale/shift, rest read g_A (384-stride).
__global__ void __launch_bounds__(256, 2) k_gemm512(const float* __restrict__ W,
                                                    const float* __restrict__ bias,
                                                    int act, int stats_layer,
                                                    const float* __restrict__ bng,
                                                    const float* __restrict__ bnb,
                                                    int bn_layer) {
    __shared__ __align__(16) float As[2][16][132];
    __shared__ __align__(16) float Bs[2][16][128];
    __shared__ __align__(16) float s_scale[HIDDEN];
    __shared__ __align__(16) float s_shift[HIDDEN];
    int tid = threadIdx.x;
    int row0 = blockIdx.x * 128;

    if (tid < HIDDEN) {
        float sc, sh;
        bn_params(bng, bnb, bn_layer, tid, sc, sh);
        s_scale[tid] = sc;
        s_shift[tid] = sh;
    }
    __syncthreads();

    int a_m = tid >> 1;            // 0..127
    int a_k = (tid & 1) * 8;       // 0 or 8
    int b_k = tid >> 4;            // 0..15
    int b_n = (tid & 15) * 8;      // 0..120
    int tx = tid & 15, ty = tid >> 4;

    float2 acc[8][4];
#pragma unroll
    for (int i = 0; i < 8; i++)
#pragma unroll
        for (int j = 0; j < 4; j++) acc[i][j] = make_float2(0.f, 0.f);

    bool a_valid = (row0 + a_m) < NNODES;
    int arow = a_valid ? (row0 + a_m) : 0;
    const float* Yrow = &g_Y[(size_t)arow * 128];
    const float* Arow = &g_A[(size_t)arow * ASTRIDE];
    const float* Wptr = W + b_k * 128 + b_n;

    const int NT = 32;   // 512 / 16 K-tiles
    float4 A0 = make_float4(0.f, 0.f, 0.f, 0.f), A1 = A0, W0, W1;

    // A-fragment loader: kcol block of 8 never straddles k=128
#define LOAD_A(kcol)                                                        \
    do {                                                                    \
        A0 = make_float4(0.f, 0.f, 0.f, 0.f); A1 = A0;                      \
        if (a_valid) {                                                      \
            if ((kcol) < 128) {                                             \
                float4 y0 = *(const float4*)(Yrow + (kcol));                \
                float4 y1 = *(const float4*)(Yrow + (kcol) + 4);            \
                float4 c0 = *(const float4*)&s_scale[(kcol)];               \
                float4 c1 = *(const float4*)&s_scale[(kcol) + 4];           \
                float4 d0 = *(const float4*)&s_shift[(kcol)];               \
                float4 d1 = *(const float4*)&s_shift[(kcol) + 4];           \
                A0.x = y0.x * c0.x + d0.x; A0.y = y0.y * c0.y + d0.y;       \
                A0.z = y0.z * c0.z + d0.z; A0.w = y0.w * c0.w + d0.w;       \
                A1.x = y1.x * c1.x + d1.x; A1.y = y1.y * c1.y + d1.y;       \
                A1.z = y1.z * c1.z + d1.z; A1.w = y1.w * c1.w + d1.w;       \
            } else {                                                        \
                A0 = *(const float4*)(Arow + (kcol) - 128);                 \
                A1 = *(const float4*)(Arow + (kcol) - 128 + 4);             \
            }                                                               \
        }                                                                   \
    } while (0)

    // prologue: tile 0
    LOAD_A(a_k);
    W0 = *(const float4*)(Wptr);
    W1 = *(const float4*)(Wptr + 4);
    As[0][a_k + 0][a_m] = A0.x; As[0][a_k + 1][a_m] = A0.y;
    As[0][a_k + 2][a_m] = A0.z; As[0][a_k + 3][a_m] = A0.w;
    As[0][a_k + 4][a_m] = A1.x; As[0][a_k + 5][a_m] = A1.y;
    As[0][a_k + 6][a_m] = A1.z; As[0][a_k + 7][a_m] = A1.w;
    *(float4*)&Bs[0][b_k][b_n] = W0;
    *(float4*)&Bs[0][b_k][b_n + 4] = W1;

    for (int t = 0; t < NT; t++) {
        int cur = t & 1;
        if (t + 1 < NT) {
            int kt = (t + 1) * 16;
            LOAD_A(kt + a_k);
            W0 = *(const float4*)(Wptr + (size_t)kt * 128);
            W1 = *(const float4*)(Wptr + (size_t)kt * 128 + 4);
        }
        __syncthreads();

#pragma unroll
        for (int k = 0; k < 16; k++) {
            float4 af0 = *(const float4*)&As[cur][k][ty * 8];
            float4 af1 = *(const float4*)&As[cur][k][ty * 8 + 4];
            float2 bv0 = *(const float2*)&Bs[cur][k][tx * 8];
            float2 bv1 = *(const float2*)&Bs[cur][k][tx * 8 + 2];
            float2 bv2 = *(const float2*)&Bs[cur][k][tx * 8 + 4];
            float2 bv3 = *(const float2*)&Bs[cur][k][tx * 8 + 6];
            float av[8] = {af0.x, af0.y, af0.z, af0.w, af1.x, af1.y, af1.z, af1.w};
#pragma unroll
            for (int i = 0; i < 8; i++) {
                float2 ap = make_float2(av[i], av[i]);
                ffma2(acc[i][0], ap, bv0);
                ffma2(acc[i][1], ap, bv1);
                ffma2(acc[i][2], ap, bv2);
                ffma2(acc[i][3], ap, bv3);
            }
        }

        if (t + 1 < NT) {
            int nxt = (t + 1) & 1;
            As[nxt][a_k + 0][a_m] = A0.x; As[nxt][a_k + 1][a_m] = A0.y;
            As[nxt][a_k + 2][a_m] = A0.z; As[nxt][a_k + 3][a_m] = A0.w;
            As[nxt][a_k + 4][a_m] = A1.x; As[nxt][a_k + 5][a_m] = A1.y;
            As[nxt][a_k + 6][a_m] = A1.z; As[nxt][a_k + 7][a_m] = A1.w;
            *(float4*)&Bs[nxt][b_k][b_n] = W0;
            *(float4*)&Bs[nxt][b_k][b_n + 4] = W1;
        }
    }
#undef LOAD_A

    // epilogue: bias + activation + store; per-thread column stats
    float csum[8], csum2[8];
#pragma unroll
    for (int j = 0; j < 8; j++) { csum[j] = 0.f; csum2[j] = 0.f; }

#pragma unroll
    for (int i = 0; i < 8; i++) {
        int m = row0 + ty * 8 + i;
        if (m < NNODES) {
            float* yr = &g_Y[(size_t)m * 128 + tx * 8];
#pragma unroll
            for (int j = 0; j < 4; j++) {
                float2 v = acc[i][j];
                int n = tx * 8 + 2 * j;
                v.x += bias[n];
                v.y += bias[n + 1];
                if (act == 1) {
                    v.x = (v.x >= 0.f) ? v.x : NEG_SLOPE * v.x;
                    v.y = (v.y >= 0.f) ? v.y : NEG_SLOPE * v.y;
                } else if (act == 2) {
                    v.x = fmaxf(v.x, 0.f);
                    v.y = fmaxf(v.y, 0.f);
                }
                *(float2*)(yr + 2 * j) = v;
                csum[2 * j] += v.x;     csum[2 * j + 1] += v.y;
                csum2[2 * j] += v.x * v.x; csum2[2 * j + 1] += v.y * v.y;
            }
        }
    }

    if (stats_layer >= 0) {
        float* ssum = &As[0][0][0];
        float* ssum2 = &Bs[0][0][0];
        __syncthreads();
#pragma unroll
        for (int j = 0; j < 8; j++) {
            ssum[ty * 128 + tx * 8 + j] = csum[j];
            ssum2[ty * 128 + tx * 8 + j] = csum2[j];
        }
        __syncthreads();
        if (tid < 128) {
            float s = 0.f, s2 = 0.f;
#pragma unroll
            for (int g = 0; g < 16; g++) {
                s += ssum[g * 128 + tid];
                s2 += ssum2[g * 128 + tid];
            }
            atomicAdd(&g_colsum[stats_layer][tid], s);
            atomicAdd(&g_colsumsq[stats_layer][tid], s2);
        }
    }
}

// -------------------- final: row L2 normalize + head -----------------------
__global__ void k_final(const float* __restrict__ Wrep,
                        const float* __restrict__ brep,
                        float* __restrict__ out) {
    int w = blockIdx.x * (blockDim.x >> 5) + (threadIdx.x >> 5);
    int lane = threadIdx.x & 31;
    if (w >= NNODES) return;
    const float* z = &g_Y[(size_t)w * 128];
    float v0 = z[lane], v1 = z[lane + 32], v2 = z[lane + 64], v3 = z[lane + 96];
    float ss = v0 * v0 + v1 * v1 + v2 * v2 + v3 * v3;
#pragma unroll
    for (int o = 16; o > 0; o >>= 1) ss += __shfl_xor_sync(0xffffffffu, ss, o);
    float invn = 1.0f / fmaxf(sqrtf(ss), 1e-12f);
    float d[3];
#pragma unroll
    for (int j = 0; j < 3; j++) {
        float t = v0 * Wrep[lane * 3 + j] + v1 * Wrep[(lane + 32) * 3 + j]
                + v2 * Wrep[(lane + 64) * 3 + j] + v3 * Wrep[(lane + 96) * 3 + j];
#pragma unroll
        for (int o = 16; o > 0; o >>= 1) t += __shfl_xor_sync(0xffffffffu, t, o);
        d[j] = t;
    }
    if (lane == 0) {
        out[(size_t)w * 3 + 0] = d[0] * invn + brep[0];
        out[(size_t)w * 3 + 1] = d[1] * invn + brep[1];
        out[(size_t)w * 3 + 2] = d[2] * invn + brep[2];
    }
}

// ------------------------------- launch ------------------------------------
extern "C" void kernel_launch(void* const* d_in, const int* in_sizes, int n_in,
                              void* d_out, int out_size) {
    const float* x    = (const float*)d_in[0];
    const int*   ed   = (const int*)d_in[1];
    const float* W1   = (const float*)d_in[2];
    const float* b1   = (const float*)d_in[3];
    const float* W2   = (const float*)d_in[4];
    const float* b2   = (const float*)d_in[5];
    const float* W3   = (const float*)d_in[6];
    const float* b3   = (const float*)d_in[7];
    const float* W4   = (const float*)d_in[8];
    const float* b4   = (const float*)d_in[9];
    const float* g1   = (const float*)d_in[10];
    const float* be1  = (const float*)d_in[11];
    const float* g2   = (const float*)d_in[12];
    const float* be2  = (const float*)d_in[13];
    const float* g3   = (const float*)d_in[14];
    const float* be3  = (const float*)d_in[15];
    const float* Wrep = (const float*)d_in[16];
    const float* brep = (const float*)d_in[17];
    float* out = (float*)d_out;

    const int GEMM_GRID = (NNODES + 127) / 128;   // 782
    const int SPMM_GRID = (NNODES + 7) / 8;       // 12500

    // CSR build (+ staging x, stride detect)
    k_init<<<392, 256>>>(x, ed);
    k_count<<<512, 256>>>(ed);
    k_alloc<<<392, 256>>>();
    k_fill<<<512, 256>>>(ed);

    // ---- layer 1 (3 -> 128, leaky; BN1 stats fused into gemm12) ----
    k_spmm3<<<392, 256>>>(0, 3, 0, 0);
    k_spmm3<<<392, 256>>>(3, 6, 0, 1);
    k_spmm3<<<392, 256>>>(6, 9, 3, 1);
    k_gemm12<<<1024, 128>>>(W1, b1);

    // ---- layer 2 (input BN1; leaky + BN2 stats) ----
    k_spmm128<<<SPMM_GRID, 256>>>(0, 0, 0, 1, g1, be1, 0);
    k_spmm128<<<SPMM_GRID, 256>>>(0, 128, 0, 2, g1, be1, 0);
    k_spmm128<<<SPMM_GRID, 256>>>(128, 256, 0, 0, g1, be1, 0);
    k_gemm512<<<GEMM_GRID, 256>>>(W2, b2, 1, 1, g1, be1, 0);

    // ---- layer 3 (input BN2; relu + BN3 stats) ----
    k_spmm128<<<SPMM_GRID, 256>>>(0, 0, 0, 1, g2, be2, 1);
    k_spmm128<<<SPMM_GRID, 256>>>(0, 128, 0, 2, g2, be2, 1);
    k_spmm128<<<SPMM_GRID, 256>>>(128, 256, 0, 0, g2, be2, 1);
    k_gemm512<<<GEMM_GRID, 256>>>(W3, b3, 2, 2, g2, be2, 1);

    // ---- layer 4 (input BN3; no act) + L2-normalize + head ----
    k_spmm128<<<SPMM_GRID, 256>>>(0, 0, 0, 1, g3, be3, 2);
    k_spmm128<<<SPMM_GRID, 256>>>(0, 128, 0, 2, g3, be3, 2);
    k_spmm128<<<SPMM_GRID, 256>>>(128, 256, 0, 0, g3, be3, 2);
    k_gemm512<<<GEMM_GRID, 256>>>(W4, b4, 0, -1, g3, be3, 2);
    k_final<<<(NNODES + 7) / 8, 256>>>(Wrep, brep, out);
}